// round 1
// baseline (speedup 1.0000x reference)
#include <cuda_runtime.h>
#include <math_constants.h>

// ---------------------------------------------------------------------------
// PointNetConv: 3x (1x1 conv -> BN(train) -> ReLU) -> max over K neighbors
//   input  agg_feat [16384, 64, 67]  (row p = node*64 + k, channel contiguous)
//   L0: 67->64, L1: 64->64, L2: 64->128, out [16384, 128]
// Strategy: per-layer fused GEMM writes raw conv output (pre-BN) to scratch and
// accumulates deterministic per-channel sum/sumsq partials; a tiny finalize
// kernel turns them into per-channel affine (a, c) with y = relu(a*h + c),
// which the NEXT layer applies on-the-fly while loading its input tile.
// Final kernel: affine + max over K (+ relu once, since relu commutes w/ max).
// ---------------------------------------------------------------------------

#define TOTAL_ROWS (16384 * 64)          // 1,048,576 positions
#define ROWS_PB    128
#define NBLK       (TOTAL_ROWS / ROWS_PB) // 8192
#define NNODES     16384
#define EPS        1e-5f
#define PCOUNT     ((float)TOTAL_ROWS)

// ------------------------- static device scratch ---------------------------
__device__ float g_h0[TOTAL_ROWS * 64];    // raw conv0 out  (268 MB)
__device__ float g_h1[TOTAL_ROWS * 64];    // raw conv1 out  (268 MB)
__device__ float g_h2[TOTAL_ROWS * 128];   // raw conv2 out  (537 MB)
__device__ float g_psum[128 * NBLK];       // per-channel block partial sums
__device__ float g_psq [128 * NBLK];       // per-channel block partial sumsq
__device__ float g_bna[128];               // BN affine scale (current layer)
__device__ float g_bnc[128];               // BN affine shift (current layer)

// ---------------------------------------------------------------------------
// Fused GEMM + optional input BN/ReLU + per-channel stats partials.
//   X [TOTAL_ROWS, CIN] row-major, W [COUT, CIN] row-major, B [COUT]
//   H[p, o] = B[o] + sum_c W[o,c] * act(X[p,c])
//   act = BN_IN ? relu(bna[c]*x + bnc[c]) : x
// Block: 256 threads (16 row-groups x 16 col-groups), tile 128 rows x COUT.
// Thread computes 8 rows x (COUT/16) cols.
// ---------------------------------------------------------------------------
template <int CIN, int COUT, bool BN_IN>
__global__ void __launch_bounds__(256) gemm_bn_stats(
    const float* __restrict__ X,
    const float* __restrict__ W,
    const float* __restrict__ B,
    const float* __restrict__ bna,
    const float* __restrict__ bnc,
    float* __restrict__ H,
    float* __restrict__ psum,
    float* __restrict__ psq)
{
    constexpr int SX = CIN | 1;       // odd stride -> conflict-free LDS
    constexpr int TN = COUT / 16;     // cols per thread (4 or 8)

    extern __shared__ float smem[];
    float* Xs = smem;                 // ROWS_PB * SX
    float* Ws = Xs + ROWS_PB * SX;    // COUT * SX
    float* Bs = Ws + COUT * SX;       // COUT
    float* Ba = Bs + COUT;            // CIN (only if BN_IN)
    float* Bc = Ba + CIN;

    const int tid = threadIdx.x;
    const int rg  = tid >> 4;         // 0..15 row-group
    const int cg  = tid & 15;         // 0..15 col-group
    const long long row0 = (long long)blockIdx.x * ROWS_PB;

    // ---- load W (swizzled stride) + bias + BN params ----
    for (int idx = tid; idx < COUT * CIN; idx += 256) {
        int o = idx / CIN, c = idx - o * CIN;
        Ws[o * SX + c] = W[idx];
    }
    if (tid < COUT) Bs[tid] = B[tid];
    if (BN_IN) {
        if (tid < CIN) { Ba[tid] = bna[tid]; Bc[tid] = bnc[tid]; }
    }
    __syncthreads();

    // ---- load X tile, applying previous layer's BN affine + ReLU ----
    for (int idx = tid; idx < ROWS_PB * CIN; idx += 256) {
        int r = idx / CIN, c = idx - r * CIN;
        float v = X[(row0 + r) * CIN + c];
        if (BN_IN) v = fmaxf(fmaf(Ba[c], v, Bc[c]), 0.0f);
        Xs[r * SX + c] = v;
    }
    __syncthreads();

    // ---- register-tiled GEMM ----
    float acc[8][TN];
#pragma unroll
    for (int i = 0; i < 8; i++)
#pragma unroll
        for (int j = 0; j < TN; j++) acc[i][j] = 0.0f;

#pragma unroll 2
    for (int c = 0; c < CIN; c++) {
        float xv[8], wv[TN];
#pragma unroll
        for (int i = 0; i < 8; i++) xv[i] = Xs[(rg * 8 + i) * SX + c];
#pragma unroll
        for (int j = 0; j < TN; j++) wv[j] = Ws[(cg + 16 * j) * SX + c];
#pragma unroll
        for (int i = 0; i < 8; i++)
#pragma unroll
            for (int j = 0; j < TN; j++)
                acc[i][j] = fmaf(xv[i], wv[j], acc[i][j]);
    }

    // ---- epilogue: bias, store raw H, accumulate per-channel partials ----
    float ps[TN], pq[TN];
#pragma unroll
    for (int j = 0; j < TN; j++) { ps[j] = 0.0f; pq[j] = 0.0f; }

#pragma unroll
    for (int i = 0; i < 8; i++) {
        long long r = row0 + rg * 8 + i;
#pragma unroll
        for (int j = 0; j < TN; j++) {
            int o = cg + 16 * j;
            float v = acc[i][j] + Bs[o];
            H[r * COUT + o] = v;
            ps[j] += v;
            pq[j] += v * v;
        }
    }

    // ---- deterministic block reduction of partials (reuse Xs region) ----
    __syncthreads();                  // Xs is dead; reuse as reduce buffer
    float* Rs = Xs;                   // [16][COUT]
    float* Rq = Xs + 16 * COUT;       // [16][COUT]
#pragma unroll
    for (int j = 0; j < TN; j++) {
        int o = cg + 16 * j;
        Rs[rg * COUT + o] = ps[j];
        Rq[rg * COUT + o] = pq[j];
    }
    __syncthreads();
#pragma unroll
    for (int s = 8; s > 0; s >>= 1) {
        if (rg < s) {
#pragma unroll
            for (int j = 0; j < TN; j++) {
                int o = cg + 16 * j;
                Rs[rg * COUT + o] += Rs[(rg + s) * COUT + o];
                Rq[rg * COUT + o] += Rq[(rg + s) * COUT + o];
            }
        }
        __syncthreads();
    }
    if (rg == 0) {
#pragma unroll
        for (int j = 0; j < TN; j++) {
            int o = cg + 16 * j;
            psum[o * NBLK + blockIdx.x] = Rs[o];
            psq [o * NBLK + blockIdx.x] = Rq[o];
        }
    }
}

// ---------------------------------------------------------------------------
// Finalize stats: one block per channel reduces NBLK partials, computes
//   a = gamma * rsqrt(var + eps),  c = beta - mean * a
// ---------------------------------------------------------------------------
__global__ void __launch_bounds__(256) stats_finalize(
    const float* __restrict__ psum, const float* __restrict__ psq,
    const float* __restrict__ gamma, const float* __restrict__ beta,
    float* __restrict__ bna, float* __restrict__ bnc)
{
    const int o = blockIdx.x;
    const int tid = threadIdx.x;
    float s = 0.0f, q = 0.0f;
    for (int b = tid; b < NBLK; b += 256) {
        s += psum[o * NBLK + b];
        q += psq [o * NBLK + b];
    }
    __shared__ float sh[512];
    sh[tid] = s; sh[256 + tid] = q;
    __syncthreads();
    for (int st = 128; st > 0; st >>= 1) {
        if (tid < st) {
            sh[tid]       += sh[tid + st];
            sh[256 + tid] += sh[256 + tid + st];
        }
        __syncthreads();
    }
    if (tid == 0) {
        float mean = sh[0] / PCOUNT;
        float var  = sh[256] / PCOUNT - mean * mean;
        float a    = gamma[o] * rsqrtf(var + EPS);
        bna[o] = a;
        bnc[o] = beta[o] - mean * a;
    }
}

// ---------------------------------------------------------------------------
// Final: BN2 affine + max over K=64 neighbors (+ single ReLU: relu commutes
// with max). out[node, c] for node in [0,16384), c in [0,128).
// ---------------------------------------------------------------------------
__global__ void __launch_bounds__(128) final_max(
    const float* __restrict__ H2,
    const float* __restrict__ bna, const float* __restrict__ bnc,
    float* __restrict__ out)
{
    const int node = blockIdx.x;
    const int c = threadIdx.x;           // 128 channels
    const float a = bna[c], sh = bnc[c];
    const float* p = H2 + (long long)node * 64 * 128 + c;
    float m = -CUDART_INF_F;
#pragma unroll 8
    for (int k = 0; k < 64; k++)
        m = fmaxf(m, fmaf(a, p[k * 128], sh));
    out[node * 128 + c] = fmaxf(m, 0.0f);
}

// ---------------------------------------------------------------------------
// Launch
// ---------------------------------------------------------------------------
static constexpr int smem_bytes(int cin, int cout, bool bn) {
    int sx = cin | 1;
    int fl = ROWS_PB * sx + cout * sx + cout + (bn ? 2 * cin : 0);
    return fl * 4;
}

extern "C" void kernel_launch(void* const* d_in, const int* in_sizes, int n_in,
                              void* d_out, int out_size)
{
    const float* x   = (const float*)d_in[0];
    const float* w0  = (const float*)d_in[1];
    const float* b0  = (const float*)d_in[2];
    const float* gm0 = (const float*)d_in[3];
    const float* be0 = (const float*)d_in[4];
    const float* w1  = (const float*)d_in[5];
    const float* b1  = (const float*)d_in[6];
    const float* gm1 = (const float*)d_in[7];
    const float* be1 = (const float*)d_in[8];
    const float* w2  = (const float*)d_in[9];
    const float* b2  = (const float*)d_in[10];
    const float* gm2 = (const float*)d_in[11];
    const float* be2 = (const float*)d_in[12];
    float* out = (float*)d_out;

    float *h0, *h1, *h2, *psum, *psq, *bna, *bnc;
    cudaGetSymbolAddress((void**)&h0,   g_h0);
    cudaGetSymbolAddress((void**)&h1,   g_h1);
    cudaGetSymbolAddress((void**)&h2,   g_h2);
    cudaGetSymbolAddress((void**)&psum, g_psum);
    cudaGetSymbolAddress((void**)&psq,  g_psq);
    cudaGetSymbolAddress((void**)&bna,  g_bna);
    cudaGetSymbolAddress((void**)&bnc,  g_bnc);

    constexpr int S0 = smem_bytes(67, 64,  false);  // ~50.5 KB
    constexpr int S1 = smem_bytes(64, 64,  true);   // ~49.5 KB
    constexpr int S2 = smem_bytes(64, 128, true);   // ~66.0 KB
    cudaFuncSetAttribute(gemm_bn_stats<67, 64,  false>,
                         cudaFuncAttributeMaxDynamicSharedMemorySize, S0);
    cudaFuncSetAttribute(gemm_bn_stats<64, 64,  true>,
                         cudaFuncAttributeMaxDynamicSharedMemorySize, S1);
    cudaFuncSetAttribute(gemm_bn_stats<64, 128, true>,
                         cudaFuncAttributeMaxDynamicSharedMemorySize, S2);

    // Layer 0: conv(67->64) + stats
    gemm_bn_stats<67, 64, false><<<NBLK, 256, S0>>>(
        x, w0, b0, nullptr, nullptr, h0, psum, psq);
    stats_finalize<<<64, 256>>>(psum, psq, gm0, be0, bna, bnc);

    // Layer 1: bn0+relu (on load) -> conv(64->64) + stats
    gemm_bn_stats<64, 64, true><<<NBLK, 256, S1>>>(
        h0, w1, b1, bna, bnc, h1, psum, psq);
    stats_finalize<<<64, 256>>>(psum, psq, gm1, be1, bna, bnc);

    // Layer 2: bn1+relu (on load) -> conv(64->128) + stats
    gemm_bn_stats<64, 128, true><<<NBLK, 256, S2>>>(
        h1, w2, b2, bna, bnc, h2, psum, psq);
    stats_finalize<<<128, 256>>>(psum, psq, gm2, be2, bna, bnc);

    // bn2 affine + max over K + relu -> out [16384, 128]
    final_max<<<NNODES, 128>>>(h2, bna, bnc, out);
}